// round 4
// baseline (speedup 1.0000x reference)
#include <cuda_runtime.h>
#include <cuda_bf16.h>
#include <cstdint>

// DotInteraction: x [16384, 64, 128] fp32 -> upper-tri gram [16384, 2016] fp32.
// Baseline-PTX tensor path (tcgen05 not available at sm_103 w/o 'a'):
//   mma.sync.m16n8k16 bf16 + ldmatrix. x = hi + lo (bf16); D = hh + hl + lh (fp32 acc).
// 1 batch per CTA, 128 threads. 20 upper-triangle m16n8 tiles split 5-per-warp,
// grouped into <=2 row-stripes per warp -> perfect SMSP tensor balance.
// smem 34.8KB -> 6 CTAs/SM for cross-CTA load/compute overlap.

#define FF 64
#define NPAIR 2016

constexpr int ROWB = 272;            // 256B row + 16B pad: conflict-free ldmatrix
constexpr int MATB = 64 * ROWB;      // 17408 B per matrix
constexpr int SM_L = MATB;           // [H][L]
constexpr int SM_TOTAL = 2 * MATB;   // 34816 B

__device__ __forceinline__ uint32_t smem_u32(const void* p) {
    uint32_t a;
    asm("{ .reg .u64 t; cvta.to.shared.u64 t, %1; cvt.u32.u64 %0, t; }" : "=r"(a) : "l"(p));
    return a;
}
__device__ __forceinline__ void ldsm_x4(uint32_t* r, uint32_t addr) {
    asm volatile("ldmatrix.sync.aligned.m8n8.x4.shared.b16 {%0,%1,%2,%3}, [%4];"
                 : "=r"(r[0]), "=r"(r[1]), "=r"(r[2]), "=r"(r[3]) : "r"(addr));
}
__device__ __forceinline__ void ldsm_x2(uint32_t* r, uint32_t addr) {
    asm volatile("ldmatrix.sync.aligned.m8n8.x2.shared.b16 {%0,%1}, [%2];"
                 : "=r"(r[0]), "=r"(r[1]) : "r"(addr));
}
__device__ __forceinline__ void mma_bf16(float* c, const uint32_t* a, const uint32_t* b) {
    asm volatile(
        "mma.sync.aligned.m16n8k16.row.col.f32.bf16.bf16.f32 "
        "{%0,%1,%2,%3}, {%4,%5,%6,%7}, {%8,%9}, {%0,%1,%2,%3};"
        : "+f"(c[0]), "+f"(c[1]), "+f"(c[2]), "+f"(c[3])
        : "r"(a[0]), "r"(a[1]), "r"(a[2]), "r"(a[3]), "r"(b[0]), "r"(b[1]));
}

// One row-stripe group: row-tile rt (16 rows from 16*rt), NC col-tiles from c0.
template <int NC>
__device__ __forceinline__ void run_group(uint32_t baseH, uint32_t baseL,
                                          float* __restrict__ ob,
                                          int rt, int c0, int lid) {
    const int i0 = rt * 16;
    const uint32_t aoff = (uint32_t)(i0 + (lid & 15)) * ROWB + (uint32_t)(lid >> 4) * 16;
    const uint32_t boff = (uint32_t)(c0 * 8 + (lid & 7)) * ROWB + (uint32_t)((lid >> 3) & 1) * 16;
    const uint32_t aH = baseH + aoff, aL = baseL + aoff;
    const uint32_t bH = baseH + boff, bL = baseL + boff;

    float acc[NC][4];
#pragma unroll
    for (int c = 0; c < NC; ++c)
#pragma unroll
        for (int e = 0; e < 4; ++e) acc[c][e] = 0.0f;

#pragma unroll
    for (int kk = 0; kk < 8; ++kk) {
        uint32_t ah[4], al[4];
        ldsm_x4(ah, aH + kk * 32);
        ldsm_x4(al, aL + kk * 32);
#pragma unroll
        for (int c = 0; c < NC; ++c) {
            uint32_t bh[2], bl[2];
            ldsm_x2(bh, bH + c * (8 * ROWB) + kk * 32);
            ldsm_x2(bl, bL + c * (8 * ROWB) + kk * 32);
            mma_bf16(acc[c], ah, bh);   // hh
            mma_bf16(acc[c], ah, bl);   // hl
            mma_bf16(acc[c], al, bh);   // lh
        }
    }

    // epilogue: thread t holds (i0 + t/4 + 8*half, 8*(c0+c) + 2*(t%4) + d)
    const int rbase = i0 + (lid >> 2);
    const int cbase = 2 * (lid & 3);
#pragma unroll
    for (int c = 0; c < NC; ++c) {
        const int j0 = 8 * (c0 + c) + cbase;
#pragma unroll
        for (int half = 0; half < 2; ++half) {
            const int i = rbase + 8 * half;
            const int rowoff = i * (2 * FF - i - 1) / 2 - i - 1;  // out idx = rowoff + j
#pragma unroll
            for (int d = 0; d < 2; ++d) {
                const int j = j0 + d;
                if (j > i) ob[rowoff + j] = acc[c][2 * half + d];
            }
        }
    }
}

__global__ void __launch_bounds__(128) dotint_mma_kernel(const float* __restrict__ x,
                                                         float* __restrict__ out) {
    extern __shared__ char smem[];
    const uint32_t sbase = smem_u32(smem);
    const int tid = threadIdx.x;
    const int lid = tid & 31;
    const int wid = tid >> 5;

    // ---- load batch (2048 float4), split hi/lo bf16, store padded rows ----
    const float4* xg = reinterpret_cast<const float4*>(x) + (size_t)blockIdx.x * 2048;
#pragma unroll
    for (int it = 0; it < 16; ++it) {
        int idx = tid + it * 128;          // 0..2047
        int row = idx >> 5;                // 0..63
        int k4 = (idx & 31) * 4;           // element col
        float4 v = xg[idx];

        __nv_bfloat16 h0 = __float2bfloat16(v.x);
        __nv_bfloat16 h1 = __float2bfloat16(v.y);
        __nv_bfloat16 h2 = __float2bfloat16(v.z);
        __nv_bfloat16 h3 = __float2bfloat16(v.w);
        __nv_bfloat16 l0 = __float2bfloat16(v.x - __bfloat162float(h0));
        __nv_bfloat16 l1 = __float2bfloat16(v.y - __bfloat162float(h1));
        __nv_bfloat16 l2 = __float2bfloat16(v.z - __bfloat162float(h2));
        __nv_bfloat16 l3 = __float2bfloat16(v.w - __bfloat162float(h3));

        __nv_bfloat162 hp0 = __halves2bfloat162(h0, h1);
        __nv_bfloat162 hp1 = __halves2bfloat162(h2, h3);
        __nv_bfloat162 lp0 = __halves2bfloat162(l0, l1);
        __nv_bfloat162 lp1 = __halves2bfloat162(l2, l3);

        int off = row * ROWB + k4 * 2;
        *reinterpret_cast<uint2*>(smem + off) =
            make_uint2(*reinterpret_cast<uint32_t*>(&hp0), *reinterpret_cast<uint32_t*>(&hp1));
        *reinterpret_cast<uint2*>(smem + SM_L + off) =
            make_uint2(*reinterpret_cast<uint32_t*>(&lp0), *reinterpret_cast<uint32_t*>(&lp1));
    }
    __syncthreads();

    // ---- compute: 5 m16n8 tiles per warp, balanced across SMSPs ----
    float* ob = out + (size_t)blockIdx.x * NPAIR;
    const uint32_t baseH = sbase, baseL = sbase + SM_L;

    switch (wid) {
        case 0:
            run_group<5>(baseH, baseL, ob, 0, 0, lid);
            break;
        case 1:
            run_group<3>(baseH, baseL, ob, 0, 5, lid);
            run_group<2>(baseH, baseL, ob, 1, 2, lid);
            break;
        case 2:
            run_group<4>(baseH, baseL, ob, 1, 4, lid);
            run_group<1>(baseH, baseL, ob, 2, 4, lid);
            break;
        default:
            run_group<3>(baseH, baseL, ob, 2, 5, lid);
            run_group<2>(baseH, baseL, ob, 3, 6, lid);
            break;
    }
}

extern "C" void kernel_launch(void* const* d_in, const int* in_sizes, int n_in,
                              void* d_out, int out_size) {
    const float* x = (const float*)d_in[0];
    float* out = (float*)d_out;
    int nbatch = in_sizes[0] / (FF * 128);   // 16384
    cudaFuncSetAttribute(dotint_mma_kernel, cudaFuncAttributeMaxDynamicSharedMemorySize, SM_TOTAL);
    dotint_mma_kernel<<<nbatch, 128, SM_TOTAL>>>(x, out);
}